// round 1
// baseline (speedup 1.0000x reference)
#include <cuda_runtime.h>
#include <cuda_bf16.h>
#include <math.h>

// Problem constants
#define BB   32
#define TT   4096
#define DZC  128
#define NDC  32
#define DHC  128
#define GG   384            // 3*DZ
#define IND  192            // 2*ND + DH

// ---------------- scratch (no cudaMalloc allowed) ----------------
__device__ float g_gi[(size_t)BB * TT * GG];   // 192 MB, gi_all = x @ W_ih^T + b_ih

// ---------------- packed fp32x2 helpers (sm_100+) ----------------
__device__ __forceinline__ void fma2(unsigned long long& d,
                                     unsigned long long a,
                                     unsigned long long b) {
    asm("fma.rn.f32x2 %0, %1, %2, %0;" : "+l"(d) : "l"(a), "l"(b));
}
__device__ __forceinline__ unsigned long long dup2(float a) {
    unsigned long long r;
    asm("mov.b64 %0, {%1, %1};" : "=l"(r) : "f"(a));
    return r;
}
__device__ __forceinline__ void unpk(unsigned long long v, float& x, float& y) {
    asm("mov.b64 {%0, %1}, %2;" : "=f"(x), "=f"(y) : "l"(v));
}
__device__ __forceinline__ float ex2f_(float x) {
    float y; asm("ex2.approx.f32 %0, %1;" : "=f"(y) : "f"(x)); return y;
}
__device__ __forceinline__ float rcpf_(float x) {
    float y; asm("rcp.approx.f32 %0, %1;" : "=f"(y) : "f"(x)); return y;
}
__device__ __forceinline__ float sigmoidf_(float x) {
    float e = ex2f_(-1.4426950408889634f * x);
    return rcpf_(1.0f + e);
}
__device__ __forceinline__ float tanhf_(float x) {
    float xc = fminf(fmaxf(x, -20.0f), 20.0f);
    float e = ex2f_(-2.8853900817779268f * xc);   // exp(-2x)
    return (1.0f - e) * rcpf_(1.0f + e);
}

// =====================================================================
// Kernel 1: gi_all[bt][g] = sum_k x[bt][k] * W_ih[g][k] + b_ih[g]
// x = concat(Y[32], M[32], H[128]) along k. 128x128 tile, BK=16, f32x2.
// =====================================================================
#define Bb 128
#define BN 128
#define BK 16

__global__ __launch_bounds__(256) void gi_gemm_kernel(
    const float* __restrict__ Y, const float* __restrict__ M,
    const float* __restrict__ H, const float* __restrict__ W,
    const float* __restrict__ bias, float* __restrict__ gi)
{
    __shared__ __align__(16) float As[2][BK][Bb];
    __shared__ __align__(16) float Bs[2][BK][BN];

    const int tid = threadIdx.x;
    const int bt0 = blockIdx.x * Bb;
    const int g0  = blockIdx.y * BN;
    const int tx = tid & 15;      // n-dim
    const int ty = tid >> 4;      // m-dim

    unsigned long long acc[8][4];
    #pragma unroll
    for (int i = 0; i < 8; i++)
        #pragma unroll
        for (int j = 0; j < 4; j++) acc[i][j] = 0ull;

    auto loadA = [&](int stage, int kc) {
        #pragma unroll
        for (int i = 0; i < 2; i++) {
            int e  = tid + 256 * i;
            int m  = e & 127;
            int k4 = e >> 7;                  // 0..3
            int kk = kc * BK + k4 * 4;        // global k (chunk is in one source)
            int bt = bt0 + m;
            float4 v;
            if (kk < 32)       v = *(const float4*)(Y + (size_t)bt * NDC + kk);
            else if (kk < 64)  v = *(const float4*)(M + (size_t)bt * NDC + (kk - 32));
            else               v = *(const float4*)(H + (size_t)bt * DHC + (kk - 64));
            As[stage][k4 * 4 + 0][m] = v.x;
            As[stage][k4 * 4 + 1][m] = v.y;
            As[stage][k4 * 4 + 2][m] = v.z;
            As[stage][k4 * 4 + 3][m] = v.w;
        }
    };
    auto loadB = [&](int stage, int kc) {
        #pragma unroll
        for (int i = 0; i < 2; i++) {
            int e  = tid + 256 * i;
            int g  = e & 127;
            int k4 = e >> 7;
            int kk = kc * BK + k4 * 4;
            float4 v = *(const float4*)(W + (size_t)(g0 + g) * IND + kk);
            Bs[stage][k4 * 4 + 0][g] = v.x;
            Bs[stage][k4 * 4 + 1][g] = v.y;
            Bs[stage][k4 * 4 + 2][g] = v.z;
            Bs[stage][k4 * 4 + 3][g] = v.w;
        }
    };

    loadA(0, 0); loadB(0, 0);
    __syncthreads();

    const int NKC = IND / BK;   // 12
    for (int kc = 0; kc < NKC; kc++) {
        int cur = kc & 1, nxt = cur ^ 1;
        if (kc + 1 < NKC) { loadA(nxt, kc + 1); loadB(nxt, kc + 1); }
        #pragma unroll
        for (int k = 0; k < BK; k++) {
            float a[8];
            *(float4*)&a[0] = *(const float4*)&As[cur][k][ty * 8];
            *(float4*)&a[4] = *(const float4*)&As[cur][k][ty * 8 + 4];
            unsigned long long b[4];
            {
                ulonglong2 b0 = *(const ulonglong2*)&Bs[cur][k][tx * 8];
                ulonglong2 b1 = *(const ulonglong2*)&Bs[cur][k][tx * 8 + 4];
                b[0] = b0.x; b[1] = b0.y; b[2] = b1.x; b[3] = b1.y;
            }
            #pragma unroll
            for (int i = 0; i < 8; i++) {
                unsigned long long ad = dup2(a[i]);
                fma2(acc[i][0], ad, b[0]);
                fma2(acc[i][1], ad, b[1]);
                fma2(acc[i][2], ad, b[2]);
                fma2(acc[i][3], ad, b[3]);
            }
        }
        __syncthreads();
    }

    float bia[8];
    *(float4*)&bia[0] = *(const float4*)(bias + g0 + tx * 8);
    *(float4*)&bia[4] = *(const float4*)(bias + g0 + tx * 8 + 4);

    #pragma unroll
    for (int i = 0; i < 8; i++) {
        float c[8];
        unpk(acc[i][0], c[0], c[1]);
        unpk(acc[i][1], c[2], c[3]);
        unpk(acc[i][2], c[4], c[5]);
        unpk(acc[i][3], c[6], c[7]);
        #pragma unroll
        for (int j = 0; j < 8; j++) c[j] += bia[j];
        int bt = bt0 + ty * 8 + i;
        float* out = gi + (size_t)bt * GG + g0 + tx * 8;
        *(float4*)(out)     = *(float4*)&c[0];
        *(float4*)(out + 4) = *(float4*)&c[4];
    }
}

// =====================================================================
// Kernel 2: sequential GRU scan. One CTA per batch, 384 threads.
// Thread r owns W_hh row r in registers (64 u64 = 128 regs).
// Threads 0..127 own state dim j = tid (z_j, gamma_j in registers).
// =====================================================================
__global__ __launch_bounds__(384, 1) void gru_scan_kernel(
    const float* __restrict__ z0, const float* __restrict__ t_dyn,
    const int* __restrict__ dyn_lens,
    const float* __restrict__ W_hh, const float* __restrict__ b_hh,
    const float* __restrict__ log_gamma,
    float* __restrict__ z_final, float* __restrict__ Z_traj)
{
    __shared__ __align__(16) float ts[TT];       // 16 KB: all timestamps for batch
    __shared__ __align__(16) float zbuf[DZC];    // broadcast z_d
    __shared__ float rbuf[DZC];
    __shared__ float ubuf[DZC];
    __shared__ float nbuf[DZC];

    const int b   = blockIdx.x;
    const int tid = threadIdx.x;
    const int r   = tid;          // gate row 0..383

    // Load timestamps into smem
    for (int i = tid; i < TT; i += 384) ts[i] = t_dyn[(size_t)b * TT + i];

    // W_hh row -> registers as f32x2 pairs
    unsigned long long Wp[64];
    {
        const ulonglong2* wr = (const ulonglong2*)(W_hh + (size_t)r * DZC);
        #pragma unroll
        for (int i = 0; i < 32; i++) {
            ulonglong2 v = wr[i];
            Wp[2 * i]     = v.x;
            Wp[2 * i + 1] = v.y;
        }
    }
    const float bh  = b_hh[r];
    const int   len = dyn_lens[b];
    const float* gip = g_gi + (size_t)b * TT * GG;
    float* Zout = Z_traj + (size_t)b * TT * DZC;

    float gj = 0.0f, zj = 0.0f, tprev = 0.0f, zdj = 0.0f;
    if (tid < DZC) {
        float lg = log_gamma[tid];
        gj = (lg > 20.0f) ? lg : log1pf(expf(lg));   // softplus
        zj = z0[(size_t)b * DZC + tid];
    }
    __syncthreads();
    if (tid < DZC) tprev = ts[0];

    // gi prefetch pipeline (distance 1)
    float gi_cur  = gip[r];
    float gin_cur = (tid < DZC) ? gip[256 + tid] : 0.0f;

    for (int t = 0; t < TT; t++) {
        const int tn = (t + 1 < TT) ? t + 1 : t;
        float gi_nxt  = gip[(size_t)tn * GG + r];
        float gin_nxt = (tid < DZC) ? gip[(size_t)tn * GG + 256 + tid] : 0.0f;

        if (tid < DZC) {
            float tk = ts[t];
            float dt = fmaxf(tk - tprev, 0.0f);
            tprev = tk;
            float ed = ex2f_(-1.4426950408889634f * (gj * dt));
            zdj = zj * ed;
            zbuf[tid] = zdj;
        }
        __syncthreads();   // A: zbuf ready; prev-step gate-buf reads done

        // gh[r] = W_hh[r,:] . z_d  (32 LDS.128 + 64 FFMA2)
        unsigned long long a0 = 0ull, a1 = 0ull, a2 = 0ull, a3 = 0ull;
        const ulonglong2* zb = (const ulonglong2*)zbuf;
        #pragma unroll
        for (int i = 0; i < 16; i++) {
            ulonglong2 v0 = zb[2 * i];
            ulonglong2 v1 = zb[2 * i + 1];
            fma2(a0, Wp[4 * i + 0], v0.x);
            fma2(a1, Wp[4 * i + 1], v0.y);
            fma2(a2, Wp[4 * i + 2], v1.x);
            fma2(a3, Wp[4 * i + 3], v1.y);
        }
        float x0, x1, x2, x3, x4, x5, x6, x7;
        unpk(a0, x0, x1); unpk(a1, x2, x3);
        unpk(a2, x4, x5); unpk(a3, x6, x7);
        float gh = ((x0 + x1) + (x2 + x3)) + ((x4 + x5) + (x6 + x7)) + bh;

        if (r < 128)       rbuf[r]       = sigmoidf_(gi_cur + gh);
        else if (r < 256)  ubuf[r - 128] = sigmoidf_(gi_cur + gh);
        else               nbuf[r - 256] = gh;       // hidden part of n-gate
        __syncthreads();   // B: gate buffers ready

        if (tid < DZC) {
            float rr = rbuf[tid];
            float uu = ubuf[tid];
            float hn = nbuf[tid];
            float nn = tanhf_(gin_cur + rr * hn);
            float znew = (1.0f - uu) * nn + uu * zdj;
            zj = (t < len) ? znew : zdj;
            Zout[(size_t)t * DZC + tid] = zj;
        }
        gi_cur = gi_nxt;
        gin_cur = gin_nxt;
    }

    if (tid < DZC) z_final[(size_t)b * DZC + tid] = zj;
}

// =====================================================================
// launch
// =====================================================================
extern "C" void kernel_launch(void* const* d_in, const int* in_sizes, int n_in,
                              void* d_out, int out_size)
{
    const float* z0        = (const float*)d_in[0];
    const float* t_dyn     = (const float*)d_in[1];
    const float* Y         = (const float*)d_in[2];
    const float* M         = (const float*)d_in[3];
    const int*   dyn_lens  = (const int*)  d_in[4];
    const float* H         = (const float*)d_in[5];
    const float* W_ih      = (const float*)d_in[6];
    const float* b_ih      = (const float*)d_in[7];
    const float* W_hh      = (const float*)d_in[8];
    const float* b_hh      = (const float*)d_in[9];
    const float* log_gamma = (const float*)d_in[10];

    float* out     = (float*)d_out;
    float* z_final = out;                       // (B, DZ)
    float* Z_traj  = out + (size_t)BB * DZC;    // (B, T, DZ)

    float* gi = nullptr;
    cudaGetSymbolAddress((void**)&gi, g_gi);

    dim3 ggrid((BB * TT) / Bb, GG / BN);        // (1024, 3)
    gi_gemm_kernel<<<ggrid, 256>>>(Y, M, H, W_ih, b_ih, gi);

    gru_scan_kernel<<<BB, 384>>>(z0, t_dyn, dyn_lens, W_hh, b_hh, log_gamma,
                                 z_final, Z_traj);
}